// round 8
// baseline (speedup 1.0000x reference)
#include <cuda_runtime.h>
#include <math.h>

// Problem constants
#define N        10000
#define DF       32
#define ITERS    4
#define NPAD     10240          // padded slots (multiple of 128)
#define NCHUNK   640            // 16 j per chunk
#define JSPLIT   32             // j-range splits
#define CPS      20             // chunks per split (fits 32-bit mask)
#define SPAIRS   160            // packed pairs per split (320 j)
#define ITILE    128
#define NITILE   80             // NPAD/128; grid 80*32 = 2560 blocks
#define NBINS    32768          // 32^3 Morton bins, cell size 1.0
#define ZSCALE   16384.0f
#define SENTC    50.0f

// Scratch (static device arrays; cudaMalloc is forbidden)
__device__ float  g_pairsA[(NPAD / 2) * 16];
__device__ float  g_pairsB[(NPAD / 2) * 16];
__device__ float4 g_cmetaA[NCHUNK];           // (cx,cy,cz,(3.2+rc)^2)
__device__ float4 g_cmetaB[NCHUNK];
__device__ float  g_t2A[NCHUNK];              // (1.7+rc)^2
__device__ float  g_t2B[NCHUNK];
__device__ int    g_perm[NPAD];               // slot -> original index
__device__ int    g_hist[NBINS];
__device__ int    g_binoff[NBINS];
__device__ int    g_cnt[ITERS * NITILE];      // stripe completion counters
__device__ float  g_part[JSPLIT * NPAD * 12];
__device__ float  g_h[ITERS * N * DF];
__device__ float  g_w[ITERS * N * 3];         // unnormalized softmax weights

// ---------------------------------------------------------------------------
// Pair record (16 words per packed j-pair):
//   [0..7]  x0 x1 y0 y1 z0 z1 nu0 nu1   (nu = -0.5|x|^2)
//   [8..11] x0 y0 x1 y1                  (packed xy addends)
//   [12,13] round(z*2^14) s32
// ---------------------------------------------------------------------------
__device__ __forceinline__ void write_rec(float* buf, int s, float x, float y, float z) {
    int p = s >> 1, h = s & 1;
    float nu = -0.5f * (x * x + y * y + z * z);
    float* rec = buf + p * 16;
    rec[0 + h] = x;
    rec[2 + h] = y;
    rec[4 + h] = z;
    rec[6 + h] = nu;
    rec[8 + 2 * h] = x;
    rec[9 + 2 * h] = y;
    ((int*)rec)[12 + h] = __float2int_rn(z * ZSCALE);
}

// 3D Morton spread (5 bits used)
__device__ __forceinline__ unsigned spread3(unsigned x) {
    x &= 0x3FF;
    x = (x | (x << 16)) & 0x030000FF;
    x = (x | (x << 8))  & 0x0300F00F;
    x = (x | (x << 4))  & 0x030C30C3;
    x = (x | (x << 2))  & 0x09249249;
    return x;
}
__device__ __forceinline__ int cellkey(float x, float y, float z) {
    int cx = min(max((int)floorf(x + 16.f), 0), 31);
    int cy = min(max((int)floorf(y + 16.f), 0), 31);
    int cz = min(max((int)floorf(z + 16.f), 0), 31);
    return (int)(spread3(cx) | (spread3(cy) << 1) | (spread3(cz) << 2));
}

// ---------------------------------------------------------------------------
// Single-block sort: histogram -> scan -> scatter -> pair records -> chunk meta
// ---------------------------------------------------------------------------
__global__ void __launch_bounds__(1024, 1) sortall_kernel(const float* __restrict__ X) {
    __shared__ int aux[1024];
    int tid = threadIdx.x;   // 1024 threads

    for (int k = tid; k < NBINS; k += 1024) g_hist[k] = 0;
    if (tid < ITERS * NITILE) g_cnt[tid] = 0;
    __syncthreads();

    for (int i = tid; i < N; i += 1024)
        atomicAdd(&g_hist[cellkey(X[3*i], X[3*i+1], X[3*i+2])], 1);
    __syncthreads();

    // scan: 32 bins per thread
    int t0 = tid * 32;
    int sum = 0;
    for (int k = 0; k < 32; k++) sum += g_hist[t0 + k];
    aux[tid] = sum;
    __syncthreads();
    for (int off = 1; off < 1024; off <<= 1) {
        int v = (tid >= off) ? aux[tid - off] : 0;
        __syncthreads();
        aux[tid] += v;
        __syncthreads();
    }
    int base = aux[tid] - sum;
    for (int k = 0; k < 32; k++) {
        int h = g_hist[t0 + k];
        g_binoff[t0 + k] = base;
        base += h;
    }
    __syncthreads();

    // scatter + pair records (buffer A)
    for (int i = tid; i < N; i += 1024) {
        float x = X[3*i], y = X[3*i+1], z = X[3*i+2];
        int slot = atomicAdd(&g_binoff[cellkey(x, y, z)], 1);
        g_perm[slot] = i;
        write_rec(g_pairsA, slot, x, y, z);
    }
    for (int s = N + tid; s < NPAD; s += 1024)
        write_rec(g_pairsA, s, SENTC, SENTC, SENTC);
    __syncthreads();

    // chunk meta (16 slots per chunk)
    for (int c = tid; c < NCHUNK; c += 1024) {
        float mnx = 1e30f, mxx = -1e30f, mny = 1e30f, mxy = -1e30f, mnz = 1e30f, mxz = -1e30f;
        for (int s = c * 16; s < c * 16 + 16; s++) {
            int p = s >> 1, h = s & 1;
            float x = g_pairsA[p*16 + 0 + h];
            float y = g_pairsA[p*16 + 2 + h];
            float z = g_pairsA[p*16 + 4 + h];
            mnx = fminf(mnx, x); mxx = fmaxf(mxx, x);
            mny = fminf(mny, y); mxy = fmaxf(mxy, y);
            mnz = fminf(mnz, z); mxz = fmaxf(mxz, z);
        }
        float dx = mxx - mnx, dy = mxy - mny, dz = mxz - mnz;
        float rc = 0.5f * sqrtf(dx*dx + dy*dy + dz*dz) + 1e-3f;
        float r3 = 3.2f + rc, r2 = 1.7f + rc;
        g_cmetaA[c] = make_float4(0.5f*(mnx+mxx), 0.5f*(mny+mxy), 0.5f*(mnz+mxz), r3*r3);
        g_t2A[c] = r2 * r2;
    }
}

// ---------------------------------------------------------------------------
// Logits pipeline
// ---------------------------------------------------------------------------
__global__ void linear1_kernel(const float* __restrict__ Xfea,
                               const float* __restrict__ W1,
                               const float* __restrict__ b1) {
    int it = blockIdx.y;
    int n  = blockIdx.x * blockDim.x + threadIdx.x;
    __shared__ float sW[DF * DF];
    __shared__ float sb[DF];
    for (int k = threadIdx.x; k < DF * DF; k += blockDim.x) sW[k] = W1[it * DF * DF + k];
    if (threadIdx.x < DF) sb[threadIdx.x] = b1[it * DF + threadIdx.x];
    __syncthreads();
    if (n >= N) return;
    float xf[DF];
    const float4* xr = (const float4*)(Xfea + n * DF);
    #pragma unroll
    for (int q = 0; q < DF / 4; q++) {
        float4 v = xr[q];
        xf[4*q] = v.x; xf[4*q+1] = v.y; xf[4*q+2] = v.z; xf[4*q+3] = v.w;
    }
    float* hout = g_h + (it * N + n) * DF;
    #pragma unroll 4
    for (int f = 0; f < DF; f++) {
        float acc = sb[f];
        #pragma unroll
        for (int k = 0; k < DF; k++) acc = fmaf(xf[k], sW[f * DF + k], acc);
        hout[f] = acc;
    }
}

// BN stats + BN + ReLU + linear2 + exp in one pass (block = one iteration)
__global__ void __launch_bounds__(1024, 1) bnlogits_kernel(const float* __restrict__ gamma,
                                const float* __restrict__ beta,
                                const float* __restrict__ W2,
                                const float* __restrict__ b2) {
    int it = blockIdx.x;
    int tid = threadIdx.x;
    int w  = tid >> 5;
    int f  = tid & 31;
    __shared__ float ss[32 * 33];
    __shared__ float sqq[32 * 33];
    __shared__ float smu[DF], sis[DF], sg[DF], sbe[DF], sW2[3 * DF], sb2[3];

    float s = 0.f, sq = 0.f;
    for (int n = w; n < N; n += 32) {
        float v = g_h[(it * N + n) * DF + f];
        s += v;
        sq = fmaf(v, v, sq);
    }
    ss [w * 33 + f] = s;
    sqq[w * 33 + f] = sq;
    if (tid < DF) { sg[tid] = gamma[it * DF + tid]; sbe[tid] = beta[it * DF + tid]; }
    if (tid < 3 * DF) sW2[tid] = W2[it * 3 * DF + tid];
    if (tid < 3)      sb2[tid] = b2[it * 3 + tid];
    __syncthreads();
    if (tid < DF) {
        float ts = 0.f, tq = 0.f;
        for (int ww = 0; ww < 32; ww++) { ts += ss[ww * 33 + f]; tq += sqq[ww * 33 + f]; }
        float mu  = ts / (float)N;
        float var = tq / (float)N - mu * mu;   // biased var (matches reference)
        smu[tid] = mu;
        sis[tid] = rsqrtf(var + 1e-5f);
    }
    __syncthreads();

    for (int n = tid; n < N; n += 1024) {
        const float* hrow = g_h + (it * N + n) * DF;
        float l0 = sb2[0], l1 = sb2[1], l2 = sb2[2];
        #pragma unroll
        for (int k = 0; k < DF; k++) {
            float a = fmaxf((hrow[k] - smu[k]) * sis[k] * sg[k] + sbe[k], 0.f);
            l0 = fmaf(a, sW2[0 * DF + k], l0);
            l1 = fmaf(a, sW2[1 * DF + k], l1);
            l2 = fmaf(a, sW2[2 * DF + k], l2);
        }
        float m = fmaxf(l0, fmaxf(l1, l2));
        float* wout = g_w + (it * N + n) * 3;
        wout[0] = expf(l0 - m);
        wout[1] = expf(l1 - m);
        wout[2] = expf(l2 - m);
    }
}

// ---------------------------------------------------------------------------
// Culled mean-shift + fused finalize (last block per i-stripe).
// ---------------------------------------------------------------------------
__global__ void __launch_bounds__(ITILE, 8) shift_kernel(float* __restrict__ out, int it) {
    __shared__ __align__(16) float sj[SPAIRS * 16];   // 10.2 KB
    __shared__ float4 smeta[CPS];
    __shared__ float st2[CPS];
    __shared__ int s_last;

    const float*  srcP  = (it & 1) ? g_pairsB : g_pairsA;
    float*        dstP  = (it & 1) ? g_pairsA : g_pairsB;
    const float4* srcM  = (it & 1) ? g_cmetaB : g_cmetaA;
    float4*       dstM  = (it & 1) ? g_cmetaA : g_cmetaB;
    const float*  srcT2 = (it & 1) ? g_t2B : g_t2A;
    float*        dstT2 = (it & 1) ? g_t2A : g_t2B;

    int js  = blockIdx.y;
    int bx  = blockIdx.x;
    int tid = threadIdx.x;

    const float4* tsrc = (const float4*)(srcP + js * SPAIRS * 16);
    float4* d4 = (float4*)sj;
    #pragma unroll
    for (int t = tid; t < SPAIRS * 4; t += ITILE) d4[t] = tsrc[t];
    if (tid < CPS) { smeta[tid] = srcM[js * CPS + tid]; st2[tid] = srcT2[js * CPS + tid]; }
    __syncthreads();

    int slot = bx * ITILE + tid;
    int pb = (slot >> 1) * 16, h = slot & 1;
    float xi  = srcP[pb + 0 + h];
    float yi  = srcP[pb + 2 + h];
    float zi  = srcP[pb + 4 + h];
    float nui = srcP[pb + 6 + h];
    float th1 = -nui - 0.02f;    // bw=0.2
    float th2 = -nui - 1.445f;   // bw=1.7
    float th3 = -nui - 5.12f;    // bw=3.2

    // per-thread exact classification, warp-union masks
    unsigned keepm = 0, fullm = 0;
    #pragma unroll
    for (int c = 0; c < CPS; c++) {
        float4 m = smeta[c];
        float dx = xi - m.x, dy = yi - m.y, dz = zi - m.z;
        float d2 = fmaf(dx, dx, fmaf(dy, dy, dz * dz));
        if (d2 <= m.w)    keepm |= (1u << c);
        if (d2 <= st2[c]) fullm |= (1u << c);
    }
    unsigned m_proc = __reduce_or_sync(0xFFFFFFFFu, keepm);
    unsigned m_full = __reduce_or_sync(0xFFFFFFFFu, fullm);
    unsigned m_b3   = m_proc & ~m_full;

    unsigned long long xi2, yi2, zi2;
    asm("mov.b64 %0, {%1, %1};" : "=l"(xi2) : "f"(xi));
    asm("mov.b64 %0, {%1, %1};" : "=l"(yi2) : "f"(yi));
    asm("mov.b64 %0, {%1, %1};" : "=l"(zi2) : "f"(zi));

    unsigned long long axy1 = 0ull, axy2 = 0ull, axy3 = 0ull;
    int   az1 = 0, az2 = 0, az3 = 0;
    int   ac1 = 0, ac2 = 0;
    float fc3 = 0.0f;

    while (m_b3) {
        int c = __ffs(m_b3) - 1;
        m_b3 &= m_b3 - 1;
        #pragma unroll
        for (int p = c * 8; p < c * 8 + 8; p++) {
            const float* rec = sj + p * 16;
            unsigned long long x01  = *(const unsigned long long*)(rec + 0);
            unsigned long long y01  = *(const unsigned long long*)(rec + 2);
            unsigned long long z01  = *(const unsigned long long*)(rec + 4);
            unsigned long long nu01 = *(const unsigned long long*)(rec + 6);
            unsigned long long xy0  = *(const unsigned long long*)(rec + 8);
            unsigned long long xy1  = *(const unsigned long long*)(rec + 10);
            int zf0 = ((const int*)rec)[12];
            int zf1 = ((const int*)rec)[13];
            asm("{\n\t"
                ".reg .b64  t64;\n\t"
                ".reg .f32  vl, vh;\n\t"
                ".reg .pred pl, ph;\n\t"
                "fma.rn.f32x2 t64, %3, %6, %9;\n\t"
                "fma.rn.f32x2 t64, %4, %7, t64;\n\t"
                "fma.rn.f32x2 t64, %5, %8, t64;\n\t"
                "mov.b64 {vl, vh}, t64;\n\t"
                "setp.ge.f32 pl, vl, %10;\n\t"
                "setp.ge.f32 ph, vh, %10;\n\t"
                "@pl add.rn.f32x2 %0, %0, %11;\n\t"
                "@pl add.s32 %1, %1, %13;\n\t"
                "@pl add.f32 %2, %2, 0F3F800000;\n\t"
                "@ph add.rn.f32x2 %0, %0, %12;\n\t"
                "@ph add.s32 %1, %1, %14;\n\t"
                "@ph add.f32 %2, %2, 0F3F800000;\n\t"
                "}"
                : "+l"(axy3), "+r"(az3), "+f"(fc3)
                : "l"(xi2), "l"(yi2), "l"(zi2),
                  "l"(x01), "l"(y01), "l"(z01), "l"(nu01),
                  "f"(th3), "l"(xy0), "l"(xy1), "r"(zf0), "r"(zf1));
        }
    }

    while (m_full) {
        int c = __ffs(m_full) - 1;
        m_full &= m_full - 1;
        #pragma unroll
        for (int p = c * 8; p < c * 8 + 8; p++) {
            const float* rec = sj + p * 16;
            unsigned long long x01  = *(const unsigned long long*)(rec + 0);
            unsigned long long y01  = *(const unsigned long long*)(rec + 2);
            unsigned long long z01  = *(const unsigned long long*)(rec + 4);
            unsigned long long nu01 = *(const unsigned long long*)(rec + 6);
            unsigned long long xy0  = *(const unsigned long long*)(rec + 8);
            unsigned long long xy1  = *(const unsigned long long*)(rec + 10);
            int zf0 = ((const int*)rec)[12];
            int zf1 = ((const int*)rec)[13];
            asm("{\n\t"
                ".reg .b64  t64;\n\t"
                ".reg .f32  vl, vh;\n\t"
                ".reg .pred pl1, pl2, pl3, ph1, ph2, ph3;\n\t"
                "fma.rn.f32x2 t64, %9, %12, %15;\n\t"
                "fma.rn.f32x2 t64, %10, %13, t64;\n\t"
                "fma.rn.f32x2 t64, %11, %14, t64;\n\t"
                "mov.b64 {vl, vh}, t64;\n\t"
                "setp.ge.f32 pl1, vl, %16;\n\t"
                "setp.ge.f32 pl2, vl, %17;\n\t"
                "setp.ge.f32 pl3, vl, %18;\n\t"
                "setp.ge.f32 ph1, vh, %16;\n\t"
                "setp.ge.f32 ph2, vh, %17;\n\t"
                "setp.ge.f32 ph3, vh, %18;\n\t"
                "@pl1 add.rn.f32x2 %0, %0, %19;\n\t"
                "@pl1 add.s32 %3, %3, %21;\n\t"
                "@pl1 add.s32 %6, %6, 1;\n\t"
                "@pl2 add.rn.f32x2 %1, %1, %19;\n\t"
                "@pl2 add.s32 %4, %4, %21;\n\t"
                "@pl2 add.s32 %7, %7, 1;\n\t"
                "@pl3 add.rn.f32x2 %2, %2, %19;\n\t"
                "@pl3 add.s32 %5, %5, %21;\n\t"
                "@pl3 add.f32 %8, %8, 0F3F800000;\n\t"
                "@ph1 add.rn.f32x2 %0, %0, %20;\n\t"
                "@ph1 add.s32 %3, %3, %22;\n\t"
                "@ph1 add.s32 %6, %6, 1;\n\t"
                "@ph2 add.rn.f32x2 %1, %1, %20;\n\t"
                "@ph2 add.s32 %4, %4, %22;\n\t"
                "@ph2 add.s32 %7, %7, 1;\n\t"
                "@ph3 add.rn.f32x2 %2, %2, %20;\n\t"
                "@ph3 add.s32 %5, %5, %22;\n\t"
                "@ph3 add.f32 %8, %8, 0F3F800000;\n\t"
                "}"
                : "+l"(axy1), "+l"(axy2), "+l"(axy3),
                  "+r"(az1), "+r"(az2), "+r"(az3),
                  "+r"(ac1), "+r"(ac2), "+f"(fc3)
                : "l"(xi2), "l"(yi2), "l"(zi2),
                  "l"(x01), "l"(y01), "l"(z01), "l"(nu01),
                  "f"(th1), "f"(th2), "f"(th3),
                  "l"(xy0), "l"(xy1), "r"(zf0), "r"(zf1));
        }
    }

    float* dst = g_part + (js * NPAD + slot) * 12;
    ((float4*)dst)[0] = make_float4(
        __uint_as_float((unsigned)axy1), __uint_as_float((unsigned)(axy1 >> 32)),
        __uint_as_float((unsigned)axy2), __uint_as_float((unsigned)(axy2 >> 32)));
    ((float4*)dst)[1] = make_float4(
        __uint_as_float((unsigned)axy3), __uint_as_float((unsigned)(axy3 >> 32)),
        __int_as_float(az1), __int_as_float(az2));
    ((float4*)dst)[2] = make_float4(
        __int_as_float(az3), __int_as_float(ac1),
        __int_as_float(ac2), fc3);

    // last-block finalize for this i-stripe.
    // Protocol: every thread fences its partial stores, syncthreads, then tid0
    // increments the stripe counter (fence-atomic-fence gives cross-block vis).
    __threadfence();
    __syncthreads();
    if (tid == 0) {
        int old = atomicAdd(&g_cnt[it * NITILE + bx], 1);
        s_last = (old == JSPLIT - 1) ? 1 : 0;
    }
    __syncthreads();
    if (!s_last) return;
    __threadfence();

    float nx = SENTC, ny = SENTC, nz = SENTC;
    if (slot < N) {
        float sx1=0,sy1=0,sx2=0,sy2=0,sx3=0,sy3=0, c3=0.f;
        int   z1=0,z2=0,z3=0, c1=0,c2=0;
        #pragma unroll 4
        for (int js2 = 0; js2 < JSPLIT; js2++) {
            const float4* p = (const float4*)(g_part + (js2 * NPAD + slot) * 12);
            float4 v0 = p[0], v1 = p[1], v2 = p[2];
            sx1 += v0.x; sy1 += v0.y; sx2 += v0.z; sy2 += v0.w;
            sx3 += v1.x; sy3 += v1.y;
            z1 += __float_as_int(v1.z); z2 += __float_as_int(v1.w);
            z3 += __float_as_int(v2.x);
            c1 += __float_as_int(v2.y); c2 += __float_as_int(v2.z); c3 += v2.w;
        }
        float sz1 = (float)z1 * (1.0f / ZSCALE);
        float sz2 = (float)z2 * (1.0f / ZSCALE);
        float sz3 = (float)z3 * (1.0f / ZSCALE);
        int o = g_perm[slot];
        const float* wp = g_w + (it * N + o) * 3;
        float e0 = wp[0], e1 = wp[1], e2 = wp[2];
        float inv = 1.0f / (e0 + e1 + e2);
        float r1 = e0 / (float)c1, r2 = e1 / (float)c2, r3 = e2 / c3;
        nx = (sx1 * r1 + sx2 * r2 + sx3 * r3) * inv;
        ny = (sy1 * r1 + sy2 * r2 + sy3 * r3) * inv;
        nz = (sz1 * r1 + sz2 * r2 + sz3 * r3) * inv;
        float* oo = out + (it * N + o) * 3;
        oo[0] = nx; oo[1] = ny; oo[2] = nz;
    }

    if (it < ITERS - 1) {
        write_rec(dstP, slot, nx, ny, nz);
        // chunk meta over 16-lane groups (chunk = 16 consecutive slots)
        float mnx = nx, mxx = nx, mny = ny, mxy = ny, mnz = nz, mxz = nz;
        #pragma unroll
        for (int off = 8; off >= 1; off >>= 1) {
            mnx = fminf(mnx, __shfl_xor_sync(0xFFFFFFFF, mnx, off));
            mxx = fmaxf(mxx, __shfl_xor_sync(0xFFFFFFFF, mxx, off));
            mny = fminf(mny, __shfl_xor_sync(0xFFFFFFFF, mny, off));
            mxy = fmaxf(mxy, __shfl_xor_sync(0xFFFFFFFF, mxy, off));
            mnz = fminf(mnz, __shfl_xor_sync(0xFFFFFFFF, mnz, off));
            mxz = fmaxf(mxz, __shfl_xor_sync(0xFFFFFFFF, mxz, off));
        }
        if ((tid & 15) == 0) {
            float dx = mxx - mnx, dy = mxy - mny, dz = mxz - mnz;
            float rc = 0.5f * sqrtf(dx*dx + dy*dy + dz*dz) + 1e-3f;
            float r3r = 3.2f + rc, r2r = 1.7f + rc;
            dstM [slot >> 4] = make_float4(0.5f*(mnx+mxx), 0.5f*(mny+mxy), 0.5f*(mnz+mxz), r3r*r3r);
            dstT2[slot >> 4] = r2r * r2r;
        }
    }
}

// ---------------------------------------------------------------------------
// Inputs: 0:X 1:X_fea 2:W1 3:b1 4:gamma 5:beta 6:W2 7:b2   Output: [4,N,3] f32
// Launch order: shift(it=0) at index 3 (ncu capture point). 7 launches total.
// ---------------------------------------------------------------------------
extern "C" void kernel_launch(void* const* d_in, const int* in_sizes, int n_in,
                              void* d_out, int out_size) {
    const float* X     = (const float*)d_in[0];
    const float* Xfea  = (const float*)d_in[1];
    const float* W1    = (const float*)d_in[2];
    const float* b1    = (const float*)d_in[3];
    const float* gamma = (const float*)d_in[4];
    const float* beta  = (const float*)d_in[5];
    const float* W2    = (const float*)d_in[6];
    const float* b2    = (const float*)d_in[7];
    float* out = (float*)d_out;

    linear1_kernel<<<dim3((N + 127) / 128, ITERS), 128>>>(Xfea, W1, b1);   // 0
    bnlogits_kernel<<<ITERS, 1024>>>(gamma, beta, W2, b2);                 // 1
    sortall_kernel<<<1, 1024>>>(X);                                        // 2
    for (int it = 0; it < ITERS; it++)                                     // 3..6
        shift_kernel<<<dim3(NITILE, JSPLIT), ITILE>>>(out, it);
}